// round 15
// baseline (speedup 1.0000x reference)
#include <cuda_runtime.h>
#include <cuda_bf16.h>

// AbsolutePositionEncoding: out[b][s][e] = E[s/8][e], b<64, s<2048, e<256 (fp32)
// Only objects 0..255 referenced (2048/8). Pure broadcast-write: 128 MiB stores.
//
// FINAL — verified at the hardware roofline across three clean benches
// (25.056 / 25.088 / 25.056 us; kernel 21.25-21.28 us).
//
// Roofline identification: the L2 write-ingest port (184 active LTS slices x
// 32 B sector/cycle ~= 6.3 TB/s) caps every store mechanism identically —
// pure STG (occ 30%/50%), TMA bulk stores (occ 13%), concurrent STG+TMA, and
// streaming-hint STG.cs all land at 21.2-21.6 us. 134 MB mandatory output /
// 6.31 TB/s = 21.27 us floor; measured 21.28 us. Neither DRAM (43.7%) nor
// issue (2.3%) binds. No kernel-side change can move a shared fabric cap that
// every output byte must cross exactly once.
//
// Mechanism (simplest roofline-sitter): grid (256, 4), blockIdx.x = object,
// blockIdx.y = quarter of the batch dim. Thread t holds ONE float4 of the
// object's row in a register (lane = t & 63; t and t+256 congruent mod 64)
// and issues 32 warp-contiguous STG.E.128 — full 512 B line bursts, every
// line written exactly once, 16 regs, no SMEM, no sync.

__global__ __launch_bounds__(256, 8)
void ape_broadcast_kernel(const float4* __restrict__ E4, float4* __restrict__ out4) {
    const int obj = blockIdx.x;              // 0..255
    const int t   = threadIdx.x;             // 0..255
    const int b0  = blockIdx.y * 16;         // starting batch: 0,16,32,48

    // Row of E for this object: 256 floats = 64 float4. Lane repeats mod 64.
    const float4 v = E4[obj * 64 + (t & 63)];

    // Per-batch stride = 2048*256/4 = 131072 f4. Object span within a batch:
    // obj*512 f4, length 512 f4 (256 objs * 512 = 131072 = full batch slice).
    float4* base = out4 + (size_t)b0 * 131072 + obj * 512 + t;

    #pragma unroll
    for (int b = 0; b < 16; ++b) {
        float4* p = base + (size_t)b * 131072;
        p[0]   = v;   // j = t
        p[256] = v;   // j = t + 256
    }
}

extern "C" void kernel_launch(void* const* d_in, const int* in_sizes, int n_in,
                              void* d_out, int out_size) {
    // d_in[0] = x (unused), d_in[1] = E_absolute_position [512, 256] fp32
    const float4* E4 = (const float4*)d_in[1];
    float4* out4 = (float4*)d_out;
    dim3 grid(256, 4);
    ape_broadcast_kernel<<<grid, 256>>>(E4, out4);
}